// round 17
// baseline (speedup 1.0000x reference)
#include <cuda_runtime.h>
#include <cuda_bf16.h>
#include <cstdint>

// Off-diagonal Gram sum via:
//   (1/D) sum_d [ (sum_b x2[b,d])^2 - sum_b x2[b,d]^2 ],  x2 = x*x.
//
// R17 = R16 unchanged (replication run). R16 printed the session-best
// 8.672us; this run establishes whether that is a real mean shift
// (mechanism: 147 CTAs vs 294 halves CTA-dispatch overhead, ~4.5ns/CTA
// measured => ~0.15-0.2us expected advantage) or noise (+/-0.25us band).
//
// Config: 147 CTAs x 256 thr; thread (c, h) owns one 32B chunk (8 floats)
// across 16 b-rows: 16 staged LDG.256/thread (128 data regs), packed
// f32x2 math, 8KB smem pair-exchange for s, last-block finalize.

#define B_ROWS 32
#define THREADS 256
#define HROWS 16                 // b-rows per thread
#define D_CONST 150528
#define D8_CONST (D_CONST / 8)   // 18816 = 147 * 128

__device__ double g_acc = 0.0;
__device__ unsigned int g_count = 0;

typedef unsigned long long u64;

__device__ __forceinline__ void upk2(u64 v, float& lo, float& hi) {
    asm("mov.b64 {%0, %1}, %2;" : "=f"(lo), "=f"(hi) : "l"(v));
}
__device__ __forceinline__ u64 mul2(u64 a, u64 b) {
    u64 r; asm("mul.rn.f32x2 %0, %1, %2;" : "=l"(r) : "l"(a), "l"(b)); return r;
}
__device__ __forceinline__ u64 add2(u64 a, u64 b) {
    u64 r; asm("add.rn.f32x2 %0, %1, %2;" : "=l"(r) : "l"(a), "l"(b)); return r;
}
__device__ __forceinline__ u64 fma2(u64 a, u64 b, u64 c) {
    u64 r; asm("fma.rn.f32x2 %0, %1, %2, %3;" : "=l"(r) : "l"(a), "l"(b), "l"(c)); return r;
}

struct U256 { u64 a, b, c, d; };
__device__ __forceinline__ U256 ldg256(const float* p) {
    U256 r;
    asm volatile("ld.global.v4.b64 {%0, %1, %2, %3}, [%4];"
                 : "=l"(r.a), "=l"(r.b), "=l"(r.c), "=l"(r.d)
                 : "l"(p));
    return r;
}

__global__ void __launch_bounds__(THREADS, 1)
ortho_fixed_kernel(const float* __restrict__ in, float* __restrict__ out,
                   double inv_d, int nblocks) {
    const int tid  = threadIdx.x;
    const int c    = tid & 127;                        // chunk slot in CTA
    const int h    = tid >> 7;                         // b-half 0/1
    const int col8 = blockIdx.x * 128 + c;             // 147*128 = 18816 exact

    // 16 staged 256-bit loads: rows h*16 .. h*16+15, 8 consecutive floats.
    const float* p = in + (size_t)(h * HROWS) * D_CONST + (size_t)col8 * 8;
    U256 v[HROWS];
    #pragma unroll
    for (int j = 0; j < HROWS; j++)
        v[j] = ldg256(p + (size_t)j * D_CONST);

    u64 s0 = 0ull, s1 = 0ull, s2 = 0ull, s3 = 0ull;
    u64 t0 = 0ull, t1 = 0ull, t2 = 0ull, t3 = 0ull;
    #pragma unroll
    for (int j = 0; j < HROWS; j++) {
        u64 a0 = mul2(v[j].a, v[j].a);
        u64 a1 = mul2(v[j].b, v[j].b);
        u64 a2 = mul2(v[j].c, v[j].c);
        u64 a3 = mul2(v[j].d, v[j].d);
        s0 = add2(s0, a0); t0 = fma2(a0, a0, t0);
        s1 = add2(s1, a1); t1 = fma2(a1, a1, t1);
        s2 = add2(s2, a2); t2 = fma2(a2, a2, t2);
        s3 = add2(s3, a3); t3 = fma2(a3, a3, t3);
    }

    // local x^4 sum (additive across halves)
    float ta, tb, tsum = 0.f;
    upk2(t0, ta, tb); tsum += ta + tb;
    upk2(t1, ta, tb); tsum += ta + tb;
    upk2(t2, ta, tb); tsum += ta + tb;
    upk2(t3, ta, tb); tsum += ta + tb;

    // exchange partial s between the two b-halves of each chunk (8KB smem)
    __shared__ u64 spart[THREADS][4];
    spart[tid][0] = s0; spart[tid][1] = s1;
    spart[tid][2] = s2; spart[tid][3] = s3;
    __syncthreads();

    float val = -tsum;
    if (h == 0) {
        u64 f0 = add2(s0, spart[tid + 128][0]);
        u64 f1 = add2(s1, spart[tid + 128][1]);
        u64 f2 = add2(s2, spart[tid + 128][2]);
        u64 f3 = add2(s3, spart[tid + 128][3]);
        float x, y, ss = 0.f;
        upk2(f0, x, y); ss += x * x + y * y;
        upk2(f1, x, y); ss += x * x + y * y;
        upk2(f2, x, y); ss += x * x + y * y;
        upk2(f3, x, y); ss += x * x + y * y;
        val += ss;
    }

    #pragma unroll
    for (int off = 16; off > 0; off >>= 1)
        val += __shfl_xor_sync(0xFFFFFFFFu, val, off);

    __shared__ float warp_sums[THREADS / 32];
    int lane = tid & 31;
    int wid  = tid >> 5;
    if (lane == 0) warp_sums[wid] = val;
    __syncthreads();

    if (wid == 0) {
        float blk = (lane < THREADS / 32) ? warp_sums[lane] : 0.f;
        #pragma unroll
        for (int off = 4; off > 0; off >>= 1)
            blk += __shfl_xor_sync(0xFFFFFFFFu, blk, off);
        if (lane == 0) {
            atomicAdd(&g_acc, (double)blk);
            __threadfence();
            unsigned int ticket = atomicAdd(&g_count, 1u);
            if (ticket == (unsigned int)nblocks - 1u) {
                out[0] = (float)(g_acc * inv_d);
                g_acc = 0.0;     // reset for next graph replay
                g_count = 0u;
            }
        }
    }
}

// Generic fallback (runtime shape), identical math.
__global__ void __launch_bounds__(256, 1)
ortho_generic_kernel(const float4* __restrict__ in, float* __restrict__ out,
                     int d4, double inv_d, int nblocks) {
    int idx = blockIdx.x * 256 + threadIdx.x;
    float s0 = 0.f, s1 = 0.f, s2 = 0.f, s3 = 0.f;
    float t0 = 0.f, t1 = 0.f, t2 = 0.f, t3 = 0.f;
    if (idx < d4) {
        #pragma unroll
        for (int b = 0; b < B_ROWS; b++) {
            float4 v = in[(size_t)b * d4 + idx];
            float a0 = v.x * v.x, a1 = v.y * v.y, a2 = v.z * v.z, a3 = v.w * v.w;
            s0 += a0; t0 = fmaf(a0, a0, t0);
            s1 += a1; t1 = fmaf(a1, a1, t1);
            s2 += a2; t2 = fmaf(a2, a2, t2);
            s3 += a3; t3 = fmaf(a3, a3, t3);
        }
    }
    float val = (fmaf(s0, s0, -t0) + fmaf(s1, s1, -t1))
              + (fmaf(s2, s2, -t2) + fmaf(s3, s3, -t3));
    #pragma unroll
    for (int off = 16; off > 0; off >>= 1)
        val += __shfl_xor_sync(0xFFFFFFFFu, val, off);
    __shared__ float ws[8];
    int lane = threadIdx.x & 31, wid = threadIdx.x >> 5;
    if (lane == 0) ws[wid] = val;
    __syncthreads();
    if (wid == 0) {
        float blk = (lane < 8) ? ws[lane] : 0.f;
        #pragma unroll
        for (int off = 4; off > 0; off >>= 1)
            blk += __shfl_xor_sync(0xFFFFFFFFu, blk, off);
        if (lane == 0) {
            atomicAdd(&g_acc, (double)blk);
            __threadfence();
            unsigned int ticket = atomicAdd(&g_count, 1u);
            if (ticket == (unsigned int)nblocks - 1u) {
                out[0] = (float)(g_acc * inv_d);
                g_acc = 0.0;
                g_count = 0u;
            }
        }
    }
}

extern "C" void kernel_launch(void* const* d_in, const int* in_sizes, int n_in,
                              void* d_out, int out_size) {
    int total = in_sizes[0];
    int D = total / B_ROWS;

    if (D == D_CONST) {
        int blocks = D8_CONST / 128;   // 147, exact
        ortho_fixed_kernel<<<blocks, THREADS>>>((const float*)d_in[0], (float*)d_out,
                                                1.0 / (double)D, blocks);
    } else {
        int d4 = D / 4;
        int blocks = (d4 + 255) / 256;
        ortho_generic_kernel<<<blocks, 256>>>((const float4*)d_in[0], (float*)d_out,
                                              d4, 1.0 / (double)D, blocks);
    }
}